// round 15
// baseline (speedup 1.0000x reference)
#include <cuda_runtime.h>
#include <cuda_bf16.h>
#include <math.h>

#define NV 50000
#define NE 800000
#define CH 128
#define NCLS 16
#define QNB 196   // ceil(NV/256)

// ======= internal buffers: referenced ONLY inside kernels (never from host!) =======
__device__ int   g_deg[NV];
__device__ float g_nrm[NV];          // rsqrt(indeg + 1)  [self-loop included]
__device__ int   g_dst[NE];
__device__ int   g_off[NV + 1];      // CSR by dst
__device__ int   g_cur[NV];
__device__ int   g_adj[NE];          // src ids grouped by dst
__device__ int   g_ps[QNB];
__device__ int   g_po[QNB];
__device__ __align__(16) float g_h[NV * CH];     // nrm[v] * (A @ W)[v]
__device__ __align__(16) float g_feat[NV * CH];  // layer activations

// ================= graph build =================
__global__ void f_init() {
    int i = blockIdx.x * blockDim.x + threadIdx.x;
    for (; i < NV; i += gridDim.x * blockDim.x) g_deg[i] = 0;
}

__global__ void f_edges(const int* __restrict__ e) {
    int i = blockIdx.x * blockDim.x + threadIdx.x;
    for (; i < NE; i += gridDim.x * blockDim.x) {
        int d = min(max(e[NE + i], 0), NV - 1);
        g_dst[i] = d;
        atomicAdd(&g_deg[d], 1);
    }
}

__global__ void f_norm() {
    int i = blockIdx.x * blockDim.x + threadIdx.x;
    for (; i < NV; i += gridDim.x * blockDim.x)
        g_nrm[i] = rsqrtf((float)(g_deg[i] + 1));   // deg = indeg + self loop
}

__global__ void f_scan1() {
    __shared__ int b[256];
    int t = threadIdx.x;
    int i = blockIdx.x * 256 + t;
    int v = (i < NV) ? g_deg[i] : 0;
    b[t] = v;
    __syncthreads();
    for (int o = 1; o < 256; o <<= 1) {
        int a = (t >= o) ? b[t - o] : 0;
        __syncthreads();
        b[t] += a;
        __syncthreads();
    }
    if (i < NV) g_off[i] = b[t] - v;
    if (t == 255) g_ps[blockIdx.x] = b[255];
}

__global__ void f_scan2() {
    __shared__ int b[256];
    int t = threadIdx.x;
    int v = (t < QNB) ? g_ps[t] : 0;
    b[t] = v;
    __syncthreads();
    for (int o = 1; o < 256; o <<= 1) {
        int a = (t >= o) ? b[t - o] : 0;
        __syncthreads();
        b[t] += a;
        __syncthreads();
    }
    if (t < QNB) g_po[t] = b[t] - v;
}

__global__ void f_scan3() {
    int i = blockIdx.x * blockDim.x + threadIdx.x;
    for (; i < NV; i += gridDim.x * blockDim.x) {
        int r = g_off[i] + g_po[i >> 8];
        g_off[i] = r;
        g_cur[i] = r;
    }
    if (blockIdx.x == 0 && threadIdx.x == 0) g_off[NV] = NE;
}

__global__ void f_bucket(const int* __restrict__ e) {
    int i = blockIdx.x * blockDim.x + threadIdx.x;
    for (; i < NE; i += gridDim.x * blockDim.x) {
        int s = min(max(e[i], 0), NV - 1);
        int p = atomicAdd(&g_cur[g_dst[i]], 1);
        g_adj[p] = s;
    }
}

// ======= layer-1 GEMM (naive, correct-by-construction): g_h = nrm ⊙ (x @ W1) =======
// x and W1 are genuine harness device pointers (safe as args). g_h written internally.
__global__ __launch_bounds__(128)
void f_gemm_l1(const float* __restrict__ x, const float* __restrict__ W) {
    int m = blockIdx.x;
    int n = threadIdx.x;
    __shared__ float ar[CH];
    ar[n] = x[(size_t)m * CH + n];
    __syncthreads();
    float acc = 0.f;
#pragma unroll
    for (int k = 0; k < CH; k++)
        acc = fmaf(ar[k], W[(size_t)k * CH + n], acc);
    g_h[(size_t)m * CH + n] = acc * g_nrm[m];
}

// ======= layer-2 GEMM: input g_feat read INTERNALLY (the 14-round bug, fixed) =======
__global__ __launch_bounds__(128)
void f_gemm_l2(const float* __restrict__ W) {
    int m = blockIdx.x;
    int n = threadIdx.x;
    __shared__ float ar[CH];
    ar[n] = g_feat[(size_t)m * CH + n];   // device-side read of the internal buffer
    __syncthreads();
    float acc = 0.f;
#pragma unroll
    for (int k = 0; k < CH; k++)
        acc = fmaf(ar[k], W[(size_t)k * CH + n], acc);
    g_h[(size_t)m * CH + n] = acc * g_nrm[m];
}

// ======= aggregate: self + neighbors, outer norm, bias, relu (grid-stride warps) =======
__global__ __launch_bounds__(256)
void f_agg(const float* __restrict__ bias) {
    const int w0 = (blockIdx.x * blockDim.x + threadIdx.x) >> 5;
    const int nw = (gridDim.x * blockDim.x) >> 5;
    const int l  = threadIdx.x & 31;

    for (int v = w0; v < NV; v += nw) {
        const int lo = g_off[v];
        const int hi = g_off[v + 1];

        float4 s = *(const float4*)&g_h[(size_t)v * CH + l * 4];   // self message

        int e = lo;
        for (; e + 4 <= hi; e += 4) {
            int n0 = g_adj[e], n1 = g_adj[e + 1], n2 = g_adj[e + 2], n3 = g_adj[e + 3];
            float4 u0 = *(const float4*)&g_h[(size_t)n0 * CH + l * 4];
            float4 u1 = *(const float4*)&g_h[(size_t)n1 * CH + l * 4];
            float4 u2 = *(const float4*)&g_h[(size_t)n2 * CH + l * 4];
            float4 u3 = *(const float4*)&g_h[(size_t)n3 * CH + l * 4];
            s.x += u0.x + u1.x + u2.x + u3.x;
            s.y += u0.y + u1.y + u2.y + u3.y;
            s.z += u0.z + u1.z + u2.z + u3.z;
            s.w += u0.w + u1.w + u2.w + u3.w;
        }
        for (; e < hi; e++) {
            int n = g_adj[e];
            float4 u = *(const float4*)&g_h[(size_t)n * CH + l * 4];
            s.x += u.x; s.y += u.y; s.z += u.z; s.w += u.w;
        }

        const float nv = g_nrm[v];
        float4 bb = *(const float4*)&bias[l * 4];
        float4 o;
        o.x = fmaxf(fmaf(s.x, nv, bb.x), 0.f);
        o.y = fmaxf(fmaf(s.y, nv, bb.y), 0.f);
        o.z = fmaxf(fmaf(s.z, nv, bb.z), 0.f);
        o.w = fmaxf(fmaf(s.w, nv, bb.w), 0.f);
        *(float4*)&g_feat[(size_t)v * CH + l * 4] = o;
    }
}

// ======= head: out = g_feat @ Wh + bh (g_feat read internally) =======
__global__ __launch_bounds__(256)
void f_head(const float* __restrict__ Wh, const float* __restrict__ bh,
            float* __restrict__ out) {
    __shared__ float sf[16][CH];
    __shared__ float sw[CH][NCLS];

    const int tid = threadIdx.x;
    const int rr = tid >> 4;
    const int cc = tid & 15;
    const int base = blockIdx.x * 16;

    for (int i = tid; i < 512; i += 256) {
        float4 v = *(const float4*)&Wh[i * 4];
        *(float4*)&sw[(i * 4) >> 4][(i * 4) & 15] = v;
    }
    for (int i = tid; i < 512; i += 256) {
        int m = (i * 4) >> 7, k = (i * 4) & 127;
        float4 v = make_float4(0.f, 0.f, 0.f, 0.f);
        if (base + m < NV) v = *(const float4*)&g_feat[(size_t)(base + m) * CH + k];
        *(float4*)&sf[m][k] = v;
    }
    __syncthreads();

    float a = bh[cc];
#pragma unroll 16
    for (int k = 0; k < CH; k++) a = fmaf(sf[rr][k], sw[k][cc], a);

    if (base + rr < NV)
        out[(size_t)(base + rr) * NCLS + cc] = a;
}

// ================= driver — NO device symbols referenced here =================
extern "C" void kernel_launch(void* const* d_in, const int* in_sizes, int n_in,
                              void* d_out, int out_size) {
    // resolve harness inputs by unique element count (order-robust)
    const float* x = 0; const void* ei = 0;
    const float* W1 = 0; const float* W2 = 0;
    const float* b1 = 0; const float* b2 = 0;
    const float* Wh = 0; const float* bh = 0;
    for (int i = 0; i < n_in; i++) {
        switch (in_sizes[i]) {
            case 6400000: if (!x)  x  = (const float*)d_in[i]; break;
            case 1600000: if (!ei) ei = d_in[i]; break;
            case 16384:   if (!W1) W1 = (const float*)d_in[i];
                          else if (!W2) W2 = (const float*)d_in[i]; break;
            case 128:     if (!b1) b1 = (const float*)d_in[i];
                          else if (!b2) b2 = (const float*)d_in[i]; break;
            case 2048:    if (!Wh) Wh = (const float*)d_in[i]; break;
            case 16:      if (!bh) bh = (const float*)d_in[i]; break;
            default: break;
        }
    }
    if (!x || !ei || !W1 || !W2 || !b1 || !b2 || !Wh || !bh) {
        x  = (const float*)d_in[0]; ei = d_in[1];
        W1 = (const float*)d_in[2]; b1 = (const float*)d_in[3];
        W2 = (const float*)d_in[4]; b2 = (const float*)d_in[5];
        Wh = (const float*)d_in[6]; bh = (const float*)d_in[7];
    }
    float* out = (float*)d_out;
    const int* e32 = (const int*)ei;

    f_init<<<512, 256>>>();
    f_edges<<<1024, 256>>>(e32);
    f_norm<<<512, 256>>>();
    f_scan1<<<QNB, 256>>>();
    f_scan2<<<1, 256>>>();
    f_scan3<<<512, 256>>>();
    f_bucket<<<1024, 256>>>(e32);

    // layer 1
    f_gemm_l1<<<NV, 128>>>(x, W1);
    f_agg<<<1024, 256>>>(b1);

    // layer 2  (input read internally — THE fix)
    f_gemm_l2<<<NV, 128>>>(W2);
    f_agg<<<1024, 256>>>(b2);

    // head
    f_head<<<(NV + 15) / 16, 256>>>(Wh, bh, out);
}

// round 16
// speedup vs baseline: 1.6282x; 1.6282x over previous
#include <cuda_runtime.h>
#include <cuda_bf16.h>
#include <math.h>

#define NV 50000
#define NE 800000
#define CH 128
#define NCLS 16
#define QNB 196   // ceil(NV/256)

// ======= internal buffers: referenced ONLY inside kernels (never from host!) =======
__device__ int   g_deg[NV];
__device__ float g_nrm[NV];          // rsqrt(indeg + 1)  [self-loop included]
__device__ int   g_dst[NE];
__device__ int   g_off[NV + 1];      // CSR by dst
__device__ int   g_cur[NV];
__device__ int   g_adj[NE];          // src ids grouped by dst
__device__ int   g_ps[QNB];
__device__ int   g_po[QNB];
__device__ __align__(16) float g_h[NV * CH];     // nrm[v] * (A @ W)[v]
__device__ __align__(16) float g_feat[NV * CH];  // layer activations

// ================= graph build =================
__global__ void f_init() {
    int i = blockIdx.x * blockDim.x + threadIdx.x;
    for (; i < NV; i += gridDim.x * blockDim.x) g_deg[i] = 0;
}

__global__ void f_edges(const int* __restrict__ e) {
    int i = blockIdx.x * blockDim.x + threadIdx.x;
    for (; i < NE; i += gridDim.x * blockDim.x) {
        int d = min(max(e[NE + i], 0), NV - 1);
        g_dst[i] = d;
        atomicAdd(&g_deg[d], 1);
    }
}

__global__ void f_norm() {
    int i = blockIdx.x * blockDim.x + threadIdx.x;
    for (; i < NV; i += gridDim.x * blockDim.x)
        g_nrm[i] = rsqrtf((float)(g_deg[i] + 1));   // deg = indeg + self loop
}

__global__ void f_scan1() {
    __shared__ int b[256];
    int t = threadIdx.x;
    int i = blockIdx.x * 256 + t;
    int v = (i < NV) ? g_deg[i] : 0;
    b[t] = v;
    __syncthreads();
    for (int o = 1; o < 256; o <<= 1) {
        int a = (t >= o) ? b[t - o] : 0;
        __syncthreads();
        b[t] += a;
        __syncthreads();
    }
    if (i < NV) g_off[i] = b[t] - v;
    if (t == 255) g_ps[blockIdx.x] = b[255];
}

__global__ void f_scan2() {
    __shared__ int b[256];
    int t = threadIdx.x;
    int v = (t < QNB) ? g_ps[t] : 0;
    b[t] = v;
    __syncthreads();
    for (int o = 1; o < 256; o <<= 1) {
        int a = (t >= o) ? b[t - o] : 0;
        __syncthreads();
        b[t] += a;
        __syncthreads();
    }
    if (t < QNB) g_po[t] = b[t] - v;
}

__global__ void f_scan3() {
    int i = blockIdx.x * blockDim.x + threadIdx.x;
    for (; i < NV; i += gridDim.x * blockDim.x) {
        int r = g_off[i] + g_po[i >> 8];
        g_off[i] = r;
        g_cur[i] = r;
    }
    if (blockIdx.x == 0 && threadIdx.x == 0) g_off[NV] = NE;
}

__global__ void f_bucket(const int* __restrict__ e) {
    int i = blockIdx.x * blockDim.x + threadIdx.x;
    for (; i < NE; i += gridDim.x * blockDim.x) {
        int s = min(max(e[i], 0), NV - 1);
        int p = atomicAdd(&g_cur[g_dst[i]], 1);
        g_adj[p] = s;
    }
}

// ======= tiled GEMM: g_h = nrm ⊙ (A @ W) ; A from arg (layer1) or g_feat (layer2) ======
// 128x128 output tile / block, 256 threads, 8x8 register microtile, K in chunks of 32.
template <bool FROM_FEAT>
__global__ __launch_bounds__(256, 2)
void f_gemm_tiled(const float* __restrict__ Aarg, const float* __restrict__ W) {
    __shared__ float sa[32][CH];   // sa[k][m] (A transposed)
    __shared__ float sw[32][CH];   // sw[k][n]

    const int tid = threadIdx.x;
    const int cx = tid & 15;       // col group (8 cols each)
    const int cy = tid >> 4;       // row group (8 rows each)
    const int r0 = blockIdx.x * 128;

    float acc[8][8];
#pragma unroll
    for (int a = 0; a < 8; a++)
#pragma unroll
        for (int b = 0; b < 8; b++) acc[a][b] = 0.f;

    for (int kk = 0; kk < CH; kk += 32) {
        // A tile: 128 rows x 32 k, transposed into sa
#pragma unroll
        for (int rep = 0; rep < 4; rep++) {
            int lin = tid + rep * 256;       // 0..1023 float4 slots
            int m = lin >> 3;                // 0..127
            int kq = lin & 7;                // 0..7 (k quad)
            float4 v = make_float4(0.f, 0.f, 0.f, 0.f);
            if (r0 + m < NV) {
                size_t off = (size_t)(r0 + m) * CH + kk + kq * 4;
                v = FROM_FEAT ? *(const float4*)&g_feat[off]
                              : *(const float4*)&Aarg[off];
            }
            sa[kq * 4 + 0][m] = v.x;
            sa[kq * 4 + 1][m] = v.y;
            sa[kq * 4 + 2][m] = v.z;
            sa[kq * 4 + 3][m] = v.w;
        }
        // W tile: 32 k x 128 n
#pragma unroll
        for (int rep = 0; rep < 4; rep++) {
            int lin = tid + rep * 256;
            int k = lin >> 5;                // 0..31
            int nq = lin & 31;               // 0..31
            *(float4*)&sw[k][nq * 4] = *(const float4*)&W[(size_t)(kk + k) * CH + nq * 4];
        }
        __syncthreads();

#pragma unroll 8
        for (int k = 0; k < 32; k++) {
            float ra[8], rb[8];
            *(float4*)&ra[0] = *(float4*)&sa[k][cy * 8];
            *(float4*)&ra[4] = *(float4*)&sa[k][cy * 8 + 4];
            *(float4*)&rb[0] = *(float4*)&sw[k][cx * 8];
            *(float4*)&rb[4] = *(float4*)&sw[k][cx * 8 + 4];
#pragma unroll
            for (int a = 0; a < 8; a++)
#pragma unroll
                for (int b = 0; b < 8; b++) acc[a][b] += ra[a] * rb[b];
        }
        __syncthreads();
    }

    // epilogue: fold norm, write g_h internally
#pragma unroll
    for (int a = 0; a < 8; a++) {
        int m = r0 + cy * 8 + a;
        if (m < NV) {
            float nv = g_nrm[m];
#pragma unroll
            for (int q = 0; q < 2; q++) {
                float4 o;
                o.x = acc[a][q * 4 + 0] * nv;
                o.y = acc[a][q * 4 + 1] * nv;
                o.z = acc[a][q * 4 + 2] * nv;
                o.w = acc[a][q * 4 + 3] * nv;
                *(float4*)&g_h[(size_t)m * CH + cx * 8 + q * 4] = o;
            }
        }
    }
}

// ======= aggregate: self + neighbors, outer norm, bias, relu (grid-stride warps) =======
__global__ __launch_bounds__(256)
void f_agg(const float* __restrict__ bias) {
    const int w0 = (blockIdx.x * blockDim.x + threadIdx.x) >> 5;
    const int nw = (gridDim.x * blockDim.x) >> 5;
    const int l  = threadIdx.x & 31;

    for (int v = w0; v < NV; v += nw) {
        const int lo = g_off[v];
        const int hi = g_off[v + 1];

        float4 s = *(const float4*)&g_h[(size_t)v * CH + l * 4];   // self message

        int e = lo;
        for (; e + 4 <= hi; e += 4) {
            int n0 = g_adj[e], n1 = g_adj[e + 1], n2 = g_adj[e + 2], n3 = g_adj[e + 3];
            float4 u0 = *(const float4*)&g_h[(size_t)n0 * CH + l * 4];
            float4 u1 = *(const float4*)&g_h[(size_t)n1 * CH + l * 4];
            float4 u2 = *(const float4*)&g_h[(size_t)n2 * CH + l * 4];
            float4 u3 = *(const float4*)&g_h[(size_t)n3 * CH + l * 4];
            s.x += u0.x + u1.x + u2.x + u3.x;
            s.y += u0.y + u1.y + u2.y + u3.y;
            s.z += u0.z + u1.z + u2.z + u3.z;
            s.w += u0.w + u1.w + u2.w + u3.w;
        }
        for (; e < hi; e++) {
            int n = g_adj[e];
            float4 u = *(const float4*)&g_h[(size_t)n * CH + l * 4];
            s.x += u.x; s.y += u.y; s.z += u.z; s.w += u.w;
        }

        const float nv = g_nrm[v];
        float4 bb = *(const float4*)&bias[l * 4];
        float4 o;
        o.x = fmaxf(fmaf(s.x, nv, bb.x), 0.f);
        o.y = fmaxf(fmaf(s.y, nv, bb.y), 0.f);
        o.z = fmaxf(fmaf(s.z, nv, bb.z), 0.f);
        o.w = fmaxf(fmaf(s.w, nv, bb.w), 0.f);
        *(float4*)&g_feat[(size_t)v * CH + l * 4] = o;
    }
}

// ======= head: out = g_feat @ Wh + bh (g_feat read internally) =======
__global__ __launch_bounds__(256)
void f_head(const float* __restrict__ Wh, const float* __restrict__ bh,
            float* __restrict__ out) {
    __shared__ float sf[16][CH];
    __shared__ float sw[CH][NCLS];

    const int tid = threadIdx.x;
    const int rr = tid >> 4;
    const int cc = tid & 15;
    const int base = blockIdx.x * 16;

    for (int i = tid; i < 512; i += 256) {
        float4 v = *(const float4*)&Wh[i * 4];
        *(float4*)&sw[(i * 4) >> 4][(i * 4) & 15] = v;
    }
    for (int i = tid; i < 512; i += 256) {
        int m = (i * 4) >> 7, k = (i * 4) & 127;
        float4 v = make_float4(0.f, 0.f, 0.f, 0.f);
        if (base + m < NV) v = *(const float4*)&g_feat[(size_t)(base + m) * CH + k];
        *(float4*)&sf[m][k] = v;
    }
    __syncthreads();

    float a = bh[cc];
#pragma unroll 16
    for (int k = 0; k < CH; k++) a = fmaf(sf[rr][k], sw[k][cc], a);

    if (base + rr < NV)
        out[(size_t)(base + rr) * NCLS + cc] = a;
}

// ================= driver — NO device symbols referenced here =================
extern "C" void kernel_launch(void* const* d_in, const int* in_sizes, int n_in,
                              void* d_out, int out_size) {
    const float* x = 0; const void* ei = 0;
    const float* W1 = 0; const float* W2 = 0;
    const float* b1 = 0; const float* b2 = 0;
    const float* Wh = 0; const float* bh = 0;
    for (int i = 0; i < n_in; i++) {
        switch (in_sizes[i]) {
            case 6400000: if (!x)  x  = (const float*)d_in[i]; break;
            case 1600000: if (!ei) ei = d_in[i]; break;
            case 16384:   if (!W1) W1 = (const float*)d_in[i];
                          else if (!W2) W2 = (const float*)d_in[i]; break;
            case 128:     if (!b1) b1 = (const float*)d_in[i];
                          else if (!b2) b2 = (const float*)d_in[i]; break;
            case 2048:    if (!Wh) Wh = (const float*)d_in[i]; break;
            case 16:      if (!bh) bh = (const float*)d_in[i]; break;
            default: break;
        }
    }
    if (!x || !ei || !W1 || !W2 || !b1 || !b2 || !Wh || !bh) {
        x  = (const float*)d_in[0]; ei = d_in[1];
        W1 = (const float*)d_in[2]; b1 = (const float*)d_in[3];
        W2 = (const float*)d_in[4]; b2 = (const float*)d_in[5];
        Wh = (const float*)d_in[6]; bh = (const float*)d_in[7];
    }
    float* out = (float*)d_out;
    const int* e32 = (const int*)ei;

    f_init<<<512, 256>>>();
    f_edges<<<1024, 256>>>(e32);
    f_norm<<<512, 256>>>();
    f_scan1<<<QNB, 256>>>();
    f_scan2<<<1, 256>>>();
    f_scan3<<<512, 256>>>();
    f_bucket<<<1024, 256>>>(e32);

    const int gx = (NV + 127) / 128;   // 391

    // layer 1 (A from harness pointer)
    f_gemm_tiled<false><<<gx, 256>>>(x, W1);
    f_agg<<<1024, 256>>>(b1);

    // layer 2 (A = g_feat, read inside the kernel)
    f_gemm_tiled<true><<<gx, 256>>>(nullptr, W2);
    f_agg<<<1024, 256>>>(b2);

    // head
    f_head<<<(NV + 15) / 16, 256>>>(Wh, bh, out);
}

// round 17
// speedup vs baseline: 1.7574x; 1.0793x over previous
#include <cuda_runtime.h>
#include <cuda_bf16.h>
#include <math.h>

#define NV 50000
#define NE 800000
#define CH 128
#define NCLS 16
#define QNB 196   // ceil(NV/256)

// ======= internal buffers: referenced ONLY inside kernels (never from host!) =======
__device__ int   g_deg[NV];
__device__ float g_nrm[NV];          // rsqrt(indeg + 1)  [self-loop included]
__device__ int   g_dst[NE];
__device__ int   g_off[NV + 1];      // CSR by dst
__device__ int   g_cur[NV];
__device__ int   g_adj[NE];          // src ids grouped by dst
__device__ int   g_ps[QNB];
__device__ int   g_po[QNB];
__device__ __align__(16) float g_h[NV * CH];     // nrm[v] * (A @ W)[v]
__device__ __align__(16) float g_feat[NV * CH];  // layer activations

// ================= cp.async helpers =================
__device__ __forceinline__ unsigned smem_u32(const void* p) {
    return (unsigned)__cvta_generic_to_shared(p);
}
#define CP_ASYNC16(dst_u32, src_ptr) \
    asm volatile("cp.async.cg.shared.global [%0], [%1], 16;" :: "r"(dst_u32), "l"(src_ptr))
#define CP_COMMIT() asm volatile("cp.async.commit_group;" ::: "memory")
#define CP_WAIT1()  asm volatile("cp.async.wait_group 1;" ::: "memory")
#define CP_WAIT0()  asm volatile("cp.async.wait_group 0;" ::: "memory")

// ================= graph build =================
__global__ void f_init() {
    int i = blockIdx.x * blockDim.x + threadIdx.x;
    for (; i < NV; i += gridDim.x * blockDim.x) g_deg[i] = 0;
}

__global__ void f_edges(const int* __restrict__ e) {
    int i = blockIdx.x * blockDim.x + threadIdx.x;
    for (; i < NE; i += gridDim.x * blockDim.x) {
        int d = min(max(e[NE + i], 0), NV - 1);
        g_dst[i] = d;
        atomicAdd(&g_deg[d], 1);
    }
}

// scan1 + norm fused (both consume g_deg)
__global__ void f_scan1() {
    __shared__ int b[256];
    int t = threadIdx.x;
    int i = blockIdx.x * 256 + t;
    int v = (i < NV) ? g_deg[i] : 0;
    if (i < NV) g_nrm[i] = rsqrtf((float)(v + 1));   // deg = indeg + self loop
    b[t] = v;
    __syncthreads();
    for (int o = 1; o < 256; o <<= 1) {
        int a = (t >= o) ? b[t - o] : 0;
        __syncthreads();
        b[t] += a;
        __syncthreads();
    }
    if (i < NV) g_off[i] = b[t] - v;
    if (t == 255) g_ps[blockIdx.x] = b[255];
}

__global__ void f_scan2() {
    __shared__ int b[256];
    int t = threadIdx.x;
    int v = (t < QNB) ? g_ps[t] : 0;
    b[t] = v;
    __syncthreads();
    for (int o = 1; o < 256; o <<= 1) {
        int a = (t >= o) ? b[t - o] : 0;
        __syncthreads();
        b[t] += a;
        __syncthreads();
    }
    if (t < QNB) g_po[t] = b[t] - v;
}

__global__ void f_scan3() {
    int i = blockIdx.x * blockDim.x + threadIdx.x;
    for (; i < NV; i += gridDim.x * blockDim.x) {
        int r = g_off[i] + g_po[i >> 8];
        g_off[i] = r;
        g_cur[i] = r;
    }
    if (blockIdx.x == 0 && threadIdx.x == 0) g_off[NV] = NE;
}

__global__ void f_bucket(const int* __restrict__ e) {
    int i = blockIdx.x * blockDim.x + threadIdx.x;
    for (; i < NE; i += gridDim.x * blockDim.x) {
        int s = min(max(e[i], 0), NV - 1);
        int p = atomicAdd(&g_cur[g_dst[i]], 1);
        g_adj[p] = s;
    }
}

// ======= cp.async double-buffered tiled GEMM: g_h = nrm ⊙ (A @ W) =======
// 128x128 tile / block, 256 threads, 8x8 microtile. A row-major in smem
// (36-float padded rows); W row-major. Two smem buffers, one tile in flight.
#define A_PAD 36   // floats per A-tile row (32 data + 4 pad), 144B = 16B-aligned

template <bool FROM_FEAT>
__global__ __launch_bounds__(256, 2)
void f_gemm(const float* __restrict__ Aarg, const float* __restrict__ W) {
    __shared__ float sa[2][128 * A_PAD];   // 2 x 18KB
    __shared__ float sw[2][32 * CH];       // 2 x 16KB

    const int tid = threadIdx.x;
    const int cx = tid & 15;
    const int cy = tid >> 4;
    const int r0 = blockIdx.x * 128;
    const float* Abase = FROM_FEAT ? g_feat : Aarg;

    float acc[8][8];
#pragma unroll
    for (int a = 0; a < 8; a++)
#pragma unroll
        for (int b = 0; b < 8; b++) acc[a][b] = 0.f;

    // tile loader: 8 cp.async per thread (4 for A, 4 for W)
    auto load_tile = [&](int kk, int buf) {
#pragma unroll
        for (int rep = 0; rep < 4; rep++) {
            int lin = tid + rep * 256;          // A: 1024 16B-chunks
            int m = lin >> 3;                   // 0..127
            int c = lin & 7;                    // 0..7
            int gm = min(r0 + m, NV - 1);       // clamp (dup rows; masked in epilogue)
            const float* src = &Abase[(size_t)gm * CH + kk + c * 4];
            CP_ASYNC16(smem_u32(&sa[buf][m * A_PAD + c * 4]), src);
        }
#pragma unroll
        for (int rep = 0; rep < 4; rep++) {
            int lin = tid + rep * 256;          // W: 1024 16B-chunks
            int k = lin >> 5;                   // 0..31
            int c = lin & 31;                   // 0..31
            const float* src = &W[(size_t)(kk + k) * CH + c * 4];
            CP_ASYNC16(smem_u32(&sw[buf][k * CH + c * 4]), src);
        }
        CP_COMMIT();
    };

    load_tile(0, 0);

#pragma unroll
    for (int kk = 0; kk < 4; kk++) {
        const int cur = kk & 1;
        if (kk < 3) load_tile((kk + 1) * 32, cur ^ 1);
        if (kk < 3) { CP_WAIT1(); } else { CP_WAIT0(); }
        __syncthreads();

#pragma unroll 8
        for (int k = 0; k < 32; k++) {
            float rb[8];
            *(float4*)&rb[0] = *(float4*)&sw[cur][k * CH + cx * 8];
            *(float4*)&rb[4] = *(float4*)&sw[cur][k * CH + cx * 8 + 4];
            float ra[8];
#pragma unroll
            for (int a = 0; a < 8; a++)
                ra[a] = sa[cur][(cy * 8 + a) * A_PAD + k];
#pragma unroll
            for (int a = 0; a < 8; a++)
#pragma unroll
                for (int b = 0; b < 8; b++) acc[a][b] += ra[a] * rb[b];
        }
        __syncthreads();
    }

    // epilogue: fold norm, write g_h internally
#pragma unroll
    for (int a = 0; a < 8; a++) {
        int m = r0 + cy * 8 + a;
        if (m < NV) {
            float nv = g_nrm[m];
#pragma unroll
            for (int q = 0; q < 2; q++) {
                float4 o;
                o.x = acc[a][q * 4 + 0] * nv;
                o.y = acc[a][q * 4 + 1] * nv;
                o.z = acc[a][q * 4 + 2] * nv;
                o.w = acc[a][q * 4 + 3] * nv;
                *(float4*)&g_h[(size_t)m * CH + cx * 8 + q * 4] = o;
            }
        }
    }
}

// ======= aggregate: self + neighbors (unroll 8), outer norm, bias, relu =======
__global__ __launch_bounds__(256)
void f_agg(const float* __restrict__ bias) {
    const int w0 = (blockIdx.x * blockDim.x + threadIdx.x) >> 5;
    const int nw = (gridDim.x * blockDim.x) >> 5;
    const int l  = threadIdx.x & 31;

    for (int v = w0; v < NV; v += nw) {
        const int lo = g_off[v];
        const int hi = g_off[v + 1];

        float4 s = *(const float4*)&g_h[(size_t)v * CH + l * 4];   // self message

        int e = lo;
        for (; e + 8 <= hi; e += 8) {
            int n0 = g_adj[e + 0], n1 = g_adj[e + 1], n2 = g_adj[e + 2], n3 = g_adj[e + 3];
            int n4 = g_adj[e + 4], n5 = g_adj[e + 5], n6 = g_adj[e + 6], n7 = g_adj[e + 7];
            float4 u0 = *(const float4*)&g_h[(size_t)n0 * CH + l * 4];
            float4 u1 = *(const float4*)&g_h[(size_t)n1 * CH + l * 4];
            float4 u2 = *(const float4*)&g_h[(size_t)n2 * CH + l * 4];
            float4 u3 = *(const float4*)&g_h[(size_t)n3 * CH + l * 4];
            float4 u4 = *(const float4*)&g_h[(size_t)n4 * CH + l * 4];
            float4 u5 = *(const float4*)&g_h[(size_t)n5 * CH + l * 4];
            float4 u6 = *(const float4*)&g_h[(size_t)n6 * CH + l * 4];
            float4 u7 = *(const float4*)&g_h[(size_t)n7 * CH + l * 4];
            s.x += (u0.x + u1.x) + (u2.x + u3.x) + (u4.x + u5.x) + (u6.x + u7.x);
            s.y += (u0.y + u1.y) + (u2.y + u3.y) + (u4.y + u5.y) + (u6.y + u7.y);
            s.z += (u0.z + u1.z) + (u2.z + u3.z) + (u4.z + u5.z) + (u6.z + u7.z);
            s.w += (u0.w + u1.w) + (u2.w + u3.w) + (u4.w + u5.w) + (u6.w + u7.w);
        }
        for (; e < hi; e++) {
            int n = g_adj[e];
            float4 u = *(const float4*)&g_h[(size_t)n * CH + l * 4];
            s.x += u.x; s.y += u.y; s.z += u.z; s.w += u.w;
        }

        const float nv = g_nrm[v];
        float4 bb = *(const float4*)&bias[l * 4];
        float4 o;
        o.x = fmaxf(fmaf(s.x, nv, bb.x), 0.f);
        o.y = fmaxf(fmaf(s.y, nv, bb.y), 0.f);
        o.z = fmaxf(fmaf(s.z, nv, bb.z), 0.f);
        o.w = fmaxf(fmaf(s.w, nv, bb.w), 0.f);
        *(float4*)&g_feat[(size_t)v * CH + l * 4] = o;
    }
}

// ======= head: out = g_feat @ Wh + bh =======
__global__ __launch_bounds__(256)
void f_head(const float* __restrict__ Wh, const float* __restrict__ bh,
            float* __restrict__ out) {
    __shared__ float sf[16][CH];
    __shared__ float sw[CH][NCLS];

    const int tid = threadIdx.x;
    const int rr = tid >> 4;
    const int cc = tid & 15;
    const int base = blockIdx.x * 16;

    for (int i = tid; i < 512; i += 256) {
        float4 v = *(const float4*)&Wh[i * 4];
        *(float4*)&sw[(i * 4) >> 4][(i * 4) & 15] = v;
    }
    for (int i = tid; i < 512; i += 256) {
        int m = (i * 4) >> 7, k = (i * 4) & 127;
        float4 v = make_float4(0.f, 0.f, 0.f, 0.f);
        if (base + m < NV) v = *(const float4*)&g_feat[(size_t)(base + m) * CH + k];
        *(float4*)&sf[m][k] = v;
    }
    __syncthreads();

    float a = bh[cc];
#pragma unroll 16
    for (int k = 0; k < CH; k++) a = fmaf(sf[rr][k], sw[k][cc], a);

    if (base + rr < NV)
        out[(size_t)(base + rr) * NCLS + cc] = a;
}

// ================= driver — NO device symbols referenced here =================
extern "C" void kernel_launch(void* const* d_in, const int* in_sizes, int n_in,
                              void* d_out, int out_size) {
    const float* x = 0; const void* ei = 0;
    const float* W1 = 0; const float* W2 = 0;
    const float* b1 = 0; const float* b2 = 0;
    const float* Wh = 0; const float* bh = 0;
    for (int i = 0; i < n_in; i++) {
        switch (in_sizes[i]) {
            case 6400000: if (!x)  x  = (const float*)d_in[i]; break;
            case 1600000: if (!ei) ei = d_in[i]; break;
            case 16384:   if (!W1) W1 = (const float*)d_in[i];
                          else if (!W2) W2 = (const float*)d_in[i]; break;
            case 128:     if (!b1) b1 = (const float*)d_in[i];
                          else if (!b2) b2 = (const float*)d_in[i]; break;
            case 2048:    if (!Wh) Wh = (const float*)d_in[i]; break;
            case 16:      if (!bh) bh = (const float*)d_in[i]; break;
            default: break;
        }
    }
    if (!x || !ei || !W1 || !W2 || !b1 || !b2 || !Wh || !bh) {
        x  = (const float*)d_in[0]; ei = d_in[1];
        W1 = (const float*)d_in[2]; b1 = (const float*)d_in[3];
        W2 = (const float*)d_in[4]; b2 = (const float*)d_in[5];
        Wh = (const float*)d_in[6]; bh = (const float*)d_in[7];
    }
    float* out = (float*)d_out;
    const int* e32 = (const int*)ei;

    f_init<<<512, 256>>>();
    f_edges<<<1024, 256>>>(e32);
    f_scan1<<<QNB, 256>>>();     // scan + norm fused
    f_scan2<<<1, 256>>>();
    f_scan3<<<512, 256>>>();
    f_bucket<<<1024, 256>>>(e32);

    const int gx = (NV + 127) / 128;   // 391

    // layer 1 (A from harness pointer)
    f_gemm<false><<<gx, 256>>>(x, W1);
    f_agg<<<1024, 256>>>(b1);

    // layer 2 (A = g_feat, read inside the kernel)
    f_gemm<true><<<gx, 256>>>(nullptr, W2);
    f_agg<<<1024, 256>>>(b2);

    // head
    f_head<<<(NV + 15) / 16, 256>>>(Wh, bh, out);
}